// round 3
// baseline (speedup 1.0000x reference)
#include <cuda_runtime.h>
#include <cstdint>

#define NN 100000
#define DD 64
#define EE 1600000

// Scratch (allocation-free rule: __device__ globals). Each [NN, 64] fp32 = 25.6 MB.
__device__ float4 g_agg [NN * 16];
__device__ float4 g_bufA[NN * 16];
__device__ float4 g_bufB[NN * 16];

// ---------------------------------------------------------------------------
// f32x2 packed-math helpers (sm_100+ only; doubles fp32 FMA throughput)
// ---------------------------------------------------------------------------
__device__ __forceinline__ unsigned long long pack2(float a, float b) {
    unsigned long long r;
    asm("mov.b64 %0, {%1, %2};" : "=l"(r) : "f"(a), "f"(b));
    return r;
}
__device__ __forceinline__ void unpack2(unsigned long long v, float& a, float& b) {
    asm("mov.b64 {%0, %1}, %2;" : "=f"(a), "=f"(b) : "l"(v));
}
__device__ __forceinline__ unsigned long long fma2(unsigned long long a,
                                                   unsigned long long b,
                                                   unsigned long long c) {
    unsigned long long r;
    asm("fma.rn.f32x2 %0, %1, %2, %3;" : "=l"(r) : "l"(a), "l"(b), "l"(c));
    return r;
}

// ---------------------------------------------------------------------------
// agg init: agg = x (the (1+eps)*x_i self term, eps=0)
// ---------------------------------------------------------------------------
__global__ void copy_kernel(const float4* __restrict__ x) {
    int i = blockIdx.x * blockDim.x + threadIdx.x;
    if (i < NN * 16) g_agg[i] = x[i];
}

// ---------------------------------------------------------------------------
// scatter: agg[dst] += x[src], one thread per (edge, float4-chunk).
// 16 consecutive threads cover one edge's 64 floats -> fully coalesced gather,
// red.global.add.v4.f32 for the scatter (no-return atomic, 16B per lane-op).
// edge_index is int32 (JAX default x64-disabled downcasts int64 -> int32).
// ---------------------------------------------------------------------------
__global__ void scatter_kernel(const float* __restrict__ x,
                               const int* __restrict__ ei) {
    int t = blockIdx.x * blockDim.x + threadIdx.x;
    if (t >= EE * 16) return;
    int e = t >> 4;
    int c = t & 15;
    int s = ei[e];          // src row
    int d = ei[EE + e];     // dst row
    float4 v = reinterpret_cast<const float4*>(x)[s * 16 + c];
    float4* a = &g_agg[d * 16 + c];
    asm volatile("red.global.add.v4.f32 [%0], {%1, %2, %3, %4};"
                 :: "l"(a), "f"(v.x), "f"(v.y), "f"(v.z), "f"(v.w)
                 : "memory");
}

// ---------------------------------------------------------------------------
// Fused MLP: out = [relu]( [relu](in @ w1 + b1) @ w2 + b2 )
// One warp per node row. Lane owns output columns (lane, lane+32), packed as
// f32x2. Weights pre-packed into smem as float2 {w[k][j], w[k][j+32]}.
// h[k] broadcast via shfl. Optionally also writes the result into g_agg
// (the next block's self-term init), fusing the copy kernel.
// ---------------------------------------------------------------------------
template <bool TWO, bool RELU_OUT>
__global__ void mlp_kernel(const float* __restrict__ in,
                           float* __restrict__ out,
                           float* __restrict__ aggout,
                           const float* __restrict__ w1, const float* __restrict__ b1,
                           const float* __restrict__ w2, const float* __restrict__ b2) {
    __shared__ float2 w1s[DD * 32];
    __shared__ float2 w2s[DD * 32];

    int tid = threadIdx.x;
    for (int i = tid; i < DD * 32; i += blockDim.x) {
        int k = i >> 5, j = i & 31;
        w1s[i] = make_float2(w1[k * DD + j], w1[k * DD + j + 32]);
        if (TWO) w2s[i] = make_float2(w2[k * DD + j], w2[k * DD + j + 32]);
    }
    __syncthreads();

    int lane = tid & 31;
    int warp = tid >> 5;
    int row  = blockIdx.x * (blockDim.x >> 5) + warp;
    if (row >= NN) return;

    const float* hrow = in + (size_t)row * DD;
    float h0 = hrow[lane];
    float h1 = hrow[lane + 32];

    unsigned long long acc = pack2(b1[lane], b1[lane + 32]);
#pragma unroll
    for (int k = 0; k < DD; k++) {
        float hk = __shfl_sync(0xffffffffu, (k < 32) ? h0 : h1, k & 31);
        unsigned long long ww =
            *reinterpret_cast<const unsigned long long*>(&w1s[k * 32 + lane]);
        acc = fma2(ww, pack2(hk, hk), acc);
    }
    float m0, m1;
    unpack2(acc, m0, m1);

    float o0, o1;
    if (TWO) {
        m0 = fmaxf(m0, 0.0f);
        m1 = fmaxf(m1, 0.0f);
        unsigned long long acc2 = pack2(b2[lane], b2[lane + 32]);
#pragma unroll
        for (int k = 0; k < DD; k++) {
            float mk = __shfl_sync(0xffffffffu, (k < 32) ? m0 : m1, k & 31);
            unsigned long long ww =
                *reinterpret_cast<const unsigned long long*>(&w2s[k * 32 + lane]);
            acc2 = fma2(ww, pack2(mk, mk), acc2);
        }
        unpack2(acc2, o0, o1);
    } else {
        o0 = m0;
        o1 = m1;
    }
    if (RELU_OUT) {
        o0 = fmaxf(o0, 0.0f);
        o1 = fmaxf(o1, 0.0f);
    }

    size_t base = (size_t)row * DD;
    out[base + lane]      = o0;
    out[base + lane + 32] = o1;
    if (aggout) {
        aggout[base + lane]      = o0;
        aggout[base + lane + 32] = o1;
    }
}

// ---------------------------------------------------------------------------
// Launch: 3 GIN blocks + final linear.
// Inputs (metadata order): x, edge_index,
//   (w1_b, b1_b, w2_b, b2_b) x3, wf, bf
// ---------------------------------------------------------------------------
extern "C" void kernel_launch(void* const* d_in, const int* in_sizes, int n_in,
                              void* d_out, int out_size) {
    const float* x  = (const float*)d_in[0];
    const int*   ei = (const int*)d_in[1];
    const float* w1[3] = {(const float*)d_in[2], (const float*)d_in[6],  (const float*)d_in[10]};
    const float* b1[3] = {(const float*)d_in[3], (const float*)d_in[7],  (const float*)d_in[11]};
    const float* w2[3] = {(const float*)d_in[4], (const float*)d_in[8],  (const float*)d_in[12]};
    const float* b2[3] = {(const float*)d_in[5], (const float*)d_in[9],  (const float*)d_in[13]};
    const float* wf = (const float*)d_in[14];
    const float* bf = (const float*)d_in[15];
    float* out = (float*)d_out;

    float *agg, *bufA, *bufB;
    cudaGetSymbolAddress((void**)&agg,  g_agg);
    cudaGetSymbolAddress((void**)&bufA, g_bufA);
    cudaGetSymbolAddress((void**)&bufB, g_bufB);

    const int COPY_GRID    = (NN * 16 + 255) / 256;
    const int SCATTER_GRID = (EE * 16 + 255) / 256;
    const int MLP_GRID     = NN / 8;  // 8 warps (rows) per 256-thread CTA

    // ---- block 0: x -> bufA (agg init for block 1 fused into MLP) ----
    copy_kernel<<<COPY_GRID, 256>>>((const float4*)x);
    scatter_kernel<<<SCATTER_GRID, 256>>>(x, ei);
    mlp_kernel<true, true><<<MLP_GRID, 256>>>(agg, bufA, agg,
                                              w1[0], b1[0], w2[0], b2[0]);

    // ---- block 1: bufA -> bufB ----
    scatter_kernel<<<SCATTER_GRID, 256>>>(bufA, ei);
    mlp_kernel<true, true><<<MLP_GRID, 256>>>(agg, bufB, agg,
                                              w1[1], b1[1], w2[1], b2[1]);

    // ---- block 2: bufB -> bufA ----
    scatter_kernel<<<SCATTER_GRID, 256>>>(bufB, ei);
    mlp_kernel<true, true><<<MLP_GRID, 256>>>(agg, bufA, nullptr,
                                              w1[2], b1[2], w2[2], b2[2]);

    // ---- final linear: out = bufA @ wf + bf ----
    mlp_kernel<false, false><<<MLP_GRID, 256>>>(bufA, out, nullptr,
                                                wf, bf, wf, bf);
}

// round 4
// speedup vs baseline: 1.4697x; 1.4697x over previous
#include <cuda_runtime.h>
#include <cstdint>

#define NN 100000
#define DD 64
#define EE 1600000

// Scratch (__device__ globals per allocation-free rule).
__device__ float g_agg [NN * DD];   // 25.6 MB
__device__ float g_bufA[NN * DD];
__device__ float g_bufB[NN * DD];
__device__ int   g_deg   [NN];
__device__ int   g_rowptr[NN + 1];
__device__ int   g_cursor[NN];
__device__ int   g_col   [EE];

// ---------------------------------------------------------------------------
// f32x2 packed helpers (sm_100+; FFMA2 only reachable via PTX)
// ---------------------------------------------------------------------------
typedef unsigned long long ull;
__device__ __forceinline__ ull pack2(float a, float b) {
    ull r; asm("mov.b64 %0, {%1, %2};" : "=l"(r) : "f"(a), "f"(b)); return r;
}
__device__ __forceinline__ void unpack2(ull v, float& a, float& b) {
    asm("mov.b64 {%0, %1}, %2;" : "=f"(a), "=f"(b) : "l"(v));
}
__device__ __forceinline__ ull fma2(ull a, ull b, ull c) {
    ull r; asm("fma.rn.f32x2 %0, %1, %2, %3;" : "=l"(r) : "l"(a), "l"(b), "l"(c)); return r;
}

// ---------------------------------------------------------------------------
// CSR build: zero -> histogram(dst) -> exclusive scan -> fill(col by cursor)
// ---------------------------------------------------------------------------
__global__ void zero_deg_kernel() {
    int i = blockIdx.x * blockDim.x + threadIdx.x;
    if (i < NN) g_deg[i] = 0;
}

__global__ void hist_kernel(const int* __restrict__ ei) {
    int e = blockIdx.x * blockDim.x + threadIdx.x;
    if (e < EE) atomicAdd(&g_deg[ei[EE + e]], 1);
}

// Single-CTA two-level scan: 1024 threads, each owns a 98-element chunk.
__global__ void scan_kernel() {
    __shared__ int sums[1024];
    const int CH = (NN + 1023) / 1024;   // 98
    int t = threadIdx.x;
    int base = t * CH;
    int s = 0;
    for (int i = 0; i < CH; i++) {
        int idx = base + i;
        if (idx < NN) s += g_deg[idx];
    }
    sums[t] = s;
    __syncthreads();
    // Hillis-Steele inclusive scan
    for (int off = 1; off < 1024; off <<= 1) {
        int v = (t >= off) ? sums[t - off] : 0;
        __syncthreads();
        sums[t] += v;
        __syncthreads();
    }
    int prefix = (t == 0) ? 0 : sums[t - 1];
    for (int i = 0; i < CH; i++) {
        int idx = base + i;
        if (idx < NN) {
            int d = g_deg[idx];
            g_rowptr[idx] = prefix;
            g_cursor[idx] = prefix;
            prefix += d;
        }
    }
    if (t == 1023) g_rowptr[NN] = prefix;   // == EE
}

__global__ void fill_kernel(const int* __restrict__ ei) {
    int e = blockIdx.x * blockDim.x + threadIdx.x;
    if (e < EE) {
        int d = ei[EE + e];
        int p = atomicAdd(&g_cursor[d], 1);
        g_col[p] = ei[e];
    }
}

// ---------------------------------------------------------------------------
// Aggregation (gather, no atomics): one warp per dst node.
//   out[d] = in[d] + sum_{s in CSR(d)} in[s]
// Lane covers columns (lane, lane+32). Edge indices loaded coalesced once,
// broadcast via shfl.
// ---------------------------------------------------------------------------
__global__ void agg_kernel(const float* __restrict__ in,
                           float* __restrict__ out) {
    int w    = (blockIdx.x * blockDim.x + threadIdx.x) >> 5;
    int lane = threadIdx.x & 31;
    if (w >= NN) return;
    int start = g_rowptr[w];
    int end   = g_rowptr[w + 1];

    size_t rb = (size_t)w * DD;
    float a0 = in[rb + lane];
    float a1 = in[rb + lane + 32];

    for (int i = start; i < end; i += 32) {
        int n   = min(32, end - i);
        int idx = (i + lane < end) ? g_col[i + lane] : 0;
#pragma unroll 4
        for (int j = 0; j < n; j++) {
            int s = __shfl_sync(0xffffffffu, idx, j);
            size_t sb = (size_t)s * DD;
            a0 += in[sb + lane];
            a1 += in[sb + lane + 32];
        }
    }
    out[rb + lane]      = a0;
    out[rb + lane + 32] = a1;
}

// ---------------------------------------------------------------------------
// MLP: lane owns one full row (64 output cols as 32 f32x2 accumulators).
// 32 rows per warp staged through a padded smem transpose buffer (stride 66
// words: 8B-aligned pairs, bounded 2-way conflicts). Weights staged in smem,
// read as broadcast LDS.128. GEMM2 reads its input from the lane's own smem
// row (m written back after relu) -> no cross-lane traffic, regs stay <=128.
// ---------------------------------------------------------------------------
#define STRIDE 66
#define STAGE_WORDS (32 * STRIDE)          // per-warp stage
// dynamic smem: ws1 | ws2 | stage[8 warps]
#define SMEM_W1 0
#define SMEM_W2 (DD * DD)
#define SMEM_ST (2 * DD * DD)
#define SMEM_TOTAL_WORDS (2 * DD * DD + 8 * STAGE_WORDS)

template <bool TWO, bool RELU_OUT>
__global__ __launch_bounds__(256, 2) void mlp_kernel(
        const float* __restrict__ in, float* __restrict__ out,
        const float* __restrict__ w1, const float* __restrict__ b1,
        const float* __restrict__ w2, const float* __restrict__ b2) {
    extern __shared__ float sm[];
    float* ws1   = sm + SMEM_W1;
    float* ws2   = sm + SMEM_W2;
    int tid  = threadIdx.x;
    int lane = tid & 31;
    int warp = tid >> 5;
    float* stg = sm + SMEM_ST + warp * STAGE_WORDS;

    // stage weights (coalesced, all 256 threads)
    for (int i = tid; i < DD * DD; i += 256) {
        ws1[i] = w1[i];
        if (TWO) ws2[i] = w2[i];
    }

    // stage 32 input rows per warp: coalesced float2 loads -> smem
    int rowbase = blockIdx.x * 256 + warp * 32;
#pragma unroll 4
    for (int r = 0; r < 32; r++) {
        int row = rowbase + r;
        float2 v = make_float2(0.f, 0.f);
        if (row < NN)
            v = *reinterpret_cast<const float2*>(in + (size_t)row * DD + 2 * lane);
        *reinterpret_cast<float2*>(stg + r * STRIDE + 2 * lane) = v;
    }
    __syncthreads();   // weights ready (stage is warp-private but cheap to share the barrier)

    const float* hrow = stg + lane * STRIDE;   // this lane's row
    const ull* b1u = reinterpret_cast<const ull*>(b1);

    ull acc[32];
#pragma unroll
    for (int j = 0; j < 32; j++) acc[j] = b1u[j];

#pragma unroll 4
    for (int k = 0; k < DD; k++) {
        float hk = hrow[k];
        ull h2 = pack2(hk, hk);
#pragma unroll
        for (int jj = 0; jj < 16; jj++) {
            float4 wv = *reinterpret_cast<const float4*>(&ws1[k * DD + jj * 4]);
            acc[2 * jj]     = fma2(pack2(wv.x, wv.y), h2, acc[2 * jj]);
            acc[2 * jj + 1] = fma2(pack2(wv.z, wv.w), h2, acc[2 * jj + 1]);
        }
    }

    if (TWO) {
        // relu + write m back into this lane's own stage row
#pragma unroll
        for (int j = 0; j < 32; j++) {
            float a, b;
            unpack2(acc[j], a, b);
            a = fmaxf(a, 0.f); b = fmaxf(b, 0.f);
            *reinterpret_cast<float2*>(const_cast<float*>(hrow) + 2 * j) =
                make_float2(a, b);
        }
        const ull* b2u = reinterpret_cast<const ull*>(b2);
#pragma unroll
        for (int j = 0; j < 32; j++) acc[j] = b2u[j];
#pragma unroll 4
        for (int k = 0; k < DD; k++) {
            float mk = hrow[k];
            ull h2 = pack2(mk, mk);
#pragma unroll
            for (int jj = 0; jj < 16; jj++) {
                float4 wv = *reinterpret_cast<const float4*>(&ws2[k * DD + jj * 4]);
                acc[2 * jj]     = fma2(pack2(wv.x, wv.y), h2, acc[2 * jj]);
                acc[2 * jj + 1] = fma2(pack2(wv.z, wv.w), h2, acc[2 * jj + 1]);
            }
        }
    }

    // epilogue: optional relu, transpose through stage, coalesced store
#pragma unroll
    for (int j = 0; j < 32; j++) {
        float a, b;
        unpack2(acc[j], a, b);
        if (RELU_OUT) { a = fmaxf(a, 0.f); b = fmaxf(b, 0.f); }
        *reinterpret_cast<float2*>(const_cast<float*>(hrow) + 2 * j) =
            make_float2(a, b);
    }
    __syncwarp();
#pragma unroll 4
    for (int r = 0; r < 32; r++) {
        int row = rowbase + r;
        if (row < NN) {
            float2 v = *reinterpret_cast<const float2*>(stg + r * STRIDE + 2 * lane);
            *reinterpret_cast<float2*>(out + (size_t)row * DD + 2 * lane) = v;
        }
    }
}

// ---------------------------------------------------------------------------
// Launch
// ---------------------------------------------------------------------------
extern "C" void kernel_launch(void* const* d_in, const int* in_sizes, int n_in,
                              void* d_out, int out_size) {
    const float* x  = (const float*)d_in[0];
    const int*   ei = (const int*)d_in[1];
    const float* w1[3] = {(const float*)d_in[2], (const float*)d_in[6],  (const float*)d_in[10]};
    const float* b1[3] = {(const float*)d_in[3], (const float*)d_in[7],  (const float*)d_in[11]};
    const float* w2[3] = {(const float*)d_in[4], (const float*)d_in[8],  (const float*)d_in[12]};
    const float* b2[3] = {(const float*)d_in[5], (const float*)d_in[9],  (const float*)d_in[13]};
    const float* wf = (const float*)d_in[14];
    const float* bf = (const float*)d_in[15];
    float* out = (float*)d_out;

    float *agg, *bufA, *bufB;
    cudaGetSymbolAddress((void**)&agg,  g_agg);
    cudaGetSymbolAddress((void**)&bufA, g_bufA);
    cudaGetSymbolAddress((void**)&bufB, g_bufB);

    const int MLP_SMEM = SMEM_TOTAL_WORDS * 4;   // ~99.6 KB
    static bool attr_done = false;
    if (!attr_done) {
        cudaFuncSetAttribute(mlp_kernel<true, true>,
                             cudaFuncAttributeMaxDynamicSharedMemorySize, MLP_SMEM);
        cudaFuncSetAttribute(mlp_kernel<false, false>,
                             cudaFuncAttributeMaxDynamicSharedMemorySize, MLP_SMEM);
        attr_done = true;
    }

    const int EDGE_GRID = (EE + 255) / 256;
    const int AGG_GRID  = (NN * 32 + 255) / 256;   // warp per node
    const int MLP_GRID  = (NN + 255) / 256;        // 256 rows per CTA

    // CSR build (once per launch; identical every replay up to fill order)
    zero_deg_kernel<<<(NN + 255) / 256, 256>>>();
    hist_kernel<<<EDGE_GRID, 256>>>(ei);
    scan_kernel<<<1, 1024>>>();
    fill_kernel<<<EDGE_GRID, 256>>>(ei);

    // block 0
    agg_kernel<<<AGG_GRID, 256>>>(x, agg);
    mlp_kernel<true, true><<<MLP_GRID, 256, MLP_SMEM>>>(agg, bufA,
                                                        w1[0], b1[0], w2[0], b2[0]);
    // block 1
    agg_kernel<<<AGG_GRID, 256>>>(bufA, agg);
    mlp_kernel<true, true><<<MLP_GRID, 256, MLP_SMEM>>>(agg, bufB,
                                                        w1[1], b1[1], w2[1], b2[1]);
    // block 2
    agg_kernel<<<AGG_GRID, 256>>>(bufB, agg);
    mlp_kernel<true, true><<<MLP_GRID, 256, MLP_SMEM>>>(agg, bufA,
                                                        w1[2], b1[2], w2[2], b2[2]);
    // final linear
    mlp_kernel<false, false><<<MLP_GRID, 256, MLP_SMEM>>>(bufA, out,
                                                          wf, bf, wf, bf);
}